// round 1
// baseline (speedup 1.0000x reference)
#include <cuda_runtime.h>
#include <math.h>

// Problem constants (fixed shapes for this bench)
#define NTOK 4096   // B*S
#define DDIM 1024
#define HDIM 4096
#define NEXP 8
#define CAP  4096   // max tokens per expert (<= NTOK)
#define TOPK 2
#define NSLOT (NTOK*TOPK)

// GEMM tiling
#define BM 128
#define BN 128
#define BK 16
#define BKP 20      // padded K stride (conflict-free LDS)

// ---------------- scratch (device globals; no allocation in kernel_launch) --
__device__ int   g_cnt[NEXP];
__device__ int   g_off[NEXP];
__device__ int   g_etok[NEXP * CAP];     // packed token*2+k per (expert, slot)
__device__ float g_egate[NEXP * CAP];
__device__ float g_h[(size_t)NSLOT * HDIM];      // 134 MB fp32 hidden acts
__device__ float g_ypart[(size_t)NSLOT * DDIM];  // 33.5 MB per-slot outputs

// ---------------- helpers ---------------------------------------------------
__device__ __forceinline__ unsigned f2tf(float f) {
    unsigned r;
    asm("cvt.rna.tf32.f32 %0, %1;" : "=r"(r) : "f"(f));
    return r;
}

__device__ __forceinline__ void mma_tf32(float c[4], const unsigned a[4],
                                         const unsigned b[2]) {
    asm volatile(
        "mma.sync.aligned.m16n8k8.row.col.f32.tf32.tf32.f32 "
        "{%0,%1,%2,%3}, {%4,%5,%6,%7}, {%8,%9}, {%0,%1,%2,%3};"
        : "+f"(c[0]), "+f"(c[1]), "+f"(c[2]), "+f"(c[3])
        : "r"(a[0]), "r"(a[1]), "r"(a[2]), "r"(a[3]), "r"(b[0]), "r"(b[1]));
}

// ---------------- kernel 0: zero counters ----------------------------------
__global__ void init_kernel() {
    if (threadIdx.x < NEXP) g_cnt[threadIdx.x] = 0;
}

// ---------------- kernel 1: router (fp32-exact) -----------------------------
// One warp per token. Wr cached in smem per block.
__global__ __launch_bounds__(256) void router_kernel(
    const float* __restrict__ x, const float* __restrict__ Wr,
    const float* __restrict__ br) {
    __shared__ float sWr[NEXP * DDIM];  // 32 KB
    int tid = threadIdx.x;
    for (int i = tid; i < NEXP * DDIM; i += 256) sWr[i] = Wr[i];
    __syncthreads();

    int warp = tid >> 5, lane = tid & 31;
    int tok = blockIdx.x * 8 + warp;
    if (tok >= NTOK) return;
    const float* xr = x + (size_t)tok * DDIM;

    float acc[NEXP];
#pragma unroll
    for (int e = 0; e < NEXP; e++) acc[e] = 0.f;
    for (int d = lane; d < DDIM; d += 32) {
        float xv = xr[d];
#pragma unroll
        for (int e = 0; e < NEXP; e++) acc[e] += xv * sWr[e * DDIM + d];
    }
#pragma unroll
    for (int e = 0; e < NEXP; e++) {
#pragma unroll
        for (int o = 16; o > 0; o >>= 1)
            acc[e] += __shfl_down_sync(0xffffffffu, acc[e], o);
    }
    if (lane == 0) {
        float v0 = -3.4e38f, v1 = -3.4e38f;
        int i0 = 0, i1 = 0;
#pragma unroll
        for (int e = 0; e < NEXP; e++) {
            float l = acc[e] + br[e];
            if (l > v0) { v1 = v0; i1 = i0; v0 = l; i0 = e; }
            else if (l > v1) { v1 = l; i1 = e; }
        }
        float t = expf(v1 - v0);
        float inv = 1.f / (1.f + t);
        float g0 = inv;
        float g1 = t * inv;
        int p0 = atomicAdd(&g_cnt[i0], 1);
        g_etok[i0 * CAP + p0] = tok * 2;
        g_egate[i0 * CAP + p0] = g0;
        int p1 = atomicAdd(&g_cnt[i1], 1);
        g_etok[i1 * CAP + p1] = tok * 2 + 1;
        g_egate[i1 * CAP + p1] = g1;
    }
}

// ---------------- kernel 2: exclusive prefix over counts --------------------
__global__ void prefix_kernel() {
    if (threadIdx.x == 0) {
        int s = 0;
        for (int e = 0; e < NEXP; e++) { g_off[e] = s; s += g_cnt[e]; }
    }
}

// ---------------- grouped GEMM (tf32 mma, double-buffered) ------------------
// MODE 1: h = relu(gather(x) @ W1[e]^T + b1[e])           K=DDIM, Ntot=HDIM
// MODE 2: ypart = gate * (hrows @ W2[e]^T + b2[e])        K=HDIM, Ntot=DDIM
template <int KDIM, int MODE>
__global__ __launch_bounds__(256) void moe_gemm_kernel(
    const float* __restrict__ Aglob, const float* __restrict__ Bglob,
    const float* __restrict__ bias) {
    const int NTOT = (MODE == 1) ? HDIM : DDIM;
    int e = blockIdx.z;
    int cnt = g_cnt[e];
    int m0 = blockIdx.y * BM;
    if (m0 >= cnt) return;
    int n0 = blockIdx.x * BN;
    int off = g_off[e];

    __shared__ unsigned As[2][BM][BKP];
    __shared__ unsigned Bs[2][BN][BKP];
    __shared__ int sRow[BM];    // MODE1: token id; MODE2: packed slot id
    __shared__ float sGate[BM];

    int tid = threadIdx.x;
    for (int r = tid; r < BM; r += 256) {
        int slot = m0 + r;
        if (MODE == 1) {
            sRow[r] = (slot < cnt) ? (g_etok[e * CAP + slot] >> 1) : 0;
        } else {
            sRow[r] = (slot < cnt) ? g_etok[e * CAP + slot] : 0;
            sGate[r] = (slot < cnt) ? g_egate[e * CAP + slot] : 0.f;
        }
    }
    __syncthreads();

    // loader mapping: each thread handles rows rr and rr+64, 4-col group quad
    int quad = tid & 3;
    int rr = tid >> 2;  // 0..63
    const float* aBase0;
    const float* aBase1;
    if (MODE == 1) {
        aBase0 = Aglob + (size_t)sRow[rr] * DDIM + quad * 4;
        aBase1 = Aglob + (size_t)sRow[rr + 64] * DDIM + quad * 4;
    } else {
        int ra = min(off + m0 + rr, NSLOT - 1);
        int rb = min(off + m0 + rr + 64, NSLOT - 1);
        aBase0 = g_h + (size_t)ra * HDIM + quad * 4;
        aBase1 = g_h + (size_t)rb * HDIM + quad * 4;
    }
    const float* Bexp = Bglob + (size_t)e * NTOT * KDIM;
    const float* bBase0 = Bexp + (size_t)(n0 + rr) * KDIM + quad * 4;
    const float* bBase1 = Bexp + (size_t)(n0 + rr + 64) * KDIM + quad * 4;

    float4 pa0, pa1, pb0, pb1;

#define LOADS(it)                                         \
    {                                                     \
        int kq = (it)*BK;                                 \
        pa0 = *(const float4*)(aBase0 + kq);              \
        pa1 = *(const float4*)(aBase1 + kq);              \
        pb0 = *(const float4*)(bBase0 + kq);              \
        pb1 = *(const float4*)(bBase1 + kq);              \
    }
#define STORES(bufi)                                                       \
    {                                                                      \
        uint4 u;                                                           \
        u.x = f2tf(pa0.x); u.y = f2tf(pa0.y);                              \
        u.z = f2tf(pa0.z); u.w = f2tf(pa0.w);                              \
        *(uint4*)&As[bufi][rr][quad * 4] = u;                              \
        u.x = f2tf(pa1.x); u.y = f2tf(pa1.y);                              \
        u.z = f2tf(pa1.z); u.w = f2tf(pa1.w);                              \
        *(uint4*)&As[bufi][rr + 64][quad * 4] = u;                         \
        u.x = f2tf(pb0.x); u.y = f2tf(pb0.y);                              \
        u.z = f2tf(pb0.z); u.w = f2tf(pb0.w);                              \
        *(uint4*)&Bs[bufi][rr][quad * 4] = u;                              \
        u.x = f2tf(pb1.x); u.y = f2tf(pb1.y);                              \
        u.z = f2tf(pb1.z); u.w = f2tf(pb1.w);                              \
        *(uint4*)&Bs[bufi][rr + 64][quad * 4] = u;                         \
    }

    // warp layout: 8 warps as 2(m) x 4(n); warp tile 64 x 32
    int warp = tid >> 5, lane = tid & 31;
    int wm = warp >> 2;  // 0..1
    int wn = warp & 3;   // 0..3
    int g = lane >> 2;   // 0..7
    int tig = lane & 3;  // 0..3

    float acc[4][4][4];
#pragma unroll
    for (int mf = 0; mf < 4; mf++)
#pragma unroll
        for (int nf = 0; nf < 4; nf++)
#pragma unroll
            for (int v = 0; v < 4; v++) acc[mf][nf][v] = 0.f;

    const int KITER = KDIM / BK;
    LOADS(0);
    STORES(0);
    __syncthreads();

    for (int it = 0; it < KITER; it++) {
        int buf = it & 1;
        if (it + 1 < KITER) LOADS(it + 1);

#pragma unroll
        for (int kk = 0; kk < BK; kk += 8) {
            unsigned af[4][4], bf[4][2];
#pragma unroll
            for (int mf = 0; mf < 4; mf++) {
                int r = wm * 64 + mf * 16;
                af[mf][0] = As[buf][r + g][kk + tig];
                af[mf][1] = As[buf][r + g + 8][kk + tig];
                af[mf][2] = As[buf][r + g][kk + tig + 4];
                af[mf][3] = As[buf][r + g + 8][kk + tig + 4];
            }
#pragma unroll
            for (int nf = 0; nf < 4; nf++) {
                int c = wn * 32 + nf * 8 + g;
                bf[nf][0] = Bs[buf][c][kk + tig];
                bf[nf][1] = Bs[buf][c][kk + tig + 4];
            }
#pragma unroll
            for (int mf = 0; mf < 4; mf++)
#pragma unroll
                for (int nf = 0; nf < 4; nf++)
                    mma_tf32(acc[mf][nf], af[mf], bf[nf]);
        }

        if (it + 1 < KITER) STORES((it + 1) & 1);
        __syncthreads();
    }
#undef LOADS
#undef STORES

    // epilogue
#pragma unroll
    for (int mf = 0; mf < 4; mf++) {
#pragma unroll
        for (int hh = 0; hh < 2; hh++) {
            int r = wm * 64 + mf * 16 + g + hh * 8;  // tile row
            int slot = m0 + r;
            if (slot >= cnt) continue;
#pragma unroll
            for (int nf = 0; nf < 4; nf++) {
                int c = n0 + wn * 32 + nf * 8 + 2 * tig;
                float v0 = acc[mf][nf][hh * 2 + 0];
                float v1 = acc[mf][nf][hh * 2 + 1];
                if (MODE == 1) {
                    v0 += bias[e * HDIM + c];
                    v1 += bias[e * HDIM + c + 1];
                    v0 = fmaxf(v0, 0.f);
                    v1 = fmaxf(v1, 0.f);
                    *(float2*)&g_h[(size_t)(off + slot) * HDIM + c] =
                        make_float2(v0, v1);
                } else {
                    float gte = sGate[r];
                    v0 = (v0 + bias[e * DDIM + c]) * gte;
                    v1 = (v1 + bias[e * DDIM + c + 1]) * gte;
                    int packed = sRow[r];
                    *(float2*)&g_ypart[(size_t)packed * DDIM + c] =
                        make_float2(v0, v1);
                }
            }
        }
    }
}

// ---------------- kernel 5: deterministic combine ---------------------------
__global__ void combine_kernel(float* __restrict__ out) {
    int i = blockIdx.x * blockDim.x + threadIdx.x;
    const int TOT = NTOK * DDIM / 4;
    if (i >= TOT) return;
    int n = i / (DDIM / 4);
    int dg = i % (DDIM / 4);
    const float4* yp = (const float4*)g_ypart;
    float4 a = yp[(size_t)(2 * n) * (DDIM / 4) + dg];
    float4 b = yp[(size_t)(2 * n + 1) * (DDIM / 4) + dg];
    float4 r;
    r.x = a.x + b.x;
    r.y = a.y + b.y;
    r.z = a.z + b.z;
    r.w = a.w + b.w;
    ((float4*)out)[i] = r;
}

// ---------------- launch -----------------------------------------------------
extern "C" void kernel_launch(void* const* d_in, const int* in_sizes, int n_in,
                              void* d_out, int out_size) {
    const float* x  = (const float*)d_in[0];
    const float* Wr = (const float*)d_in[1];
    const float* br = (const float*)d_in[2];
    const float* W1 = (const float*)d_in[3];
    const float* b1 = (const float*)d_in[4];
    const float* W2 = (const float*)d_in[5];
    const float* b2 = (const float*)d_in[6];
    float* out = (float*)d_out;
    (void)in_sizes; (void)n_in; (void)out_size;

    init_kernel<<<1, 32>>>();
    router_kernel<<<NTOK / 8, 256>>>(x, Wr, br);
    prefix_kernel<<<1, 1>>>();

    dim3 g1(HDIM / BN, NTOK / BM, NEXP);  // 32 x 32 x 8, early-exit on count
    moe_gemm_kernel<DDIM, 1><<<g1, 256>>>(x, W1, b1);

    dim3 g2(DDIM / BN, NTOK / BM, NEXP);  // 8 x 32 x 8
    moe_gemm_kernel<HDIM, 2><<<g2, 256>>>(nullptr, W2, b2);

    combine_kernel<<<(NTOK * DDIM / 4 + 255) / 256, 256>>>(out);
}